// round 2
// baseline (speedup 1.0000x reference)
#include <cuda_runtime.h>

// Input:  x  (B=64, C=3, H=512, W+1=513) fp32; h_orig = x[b,0,0,512], w_orig = x[b,1,0,512]
// Image data = x[b,c,:, :512]
// Output: (64, 3, 224, 224) fp32
// Semantics: resize shorter side to 256 (bilinear, half-pixel centers, jnp.round = rint),
// center-crop 224x224.

#define OUT_H 224
#define OUT_W 224
#define IN_H 512
#define IN_W_STRIDE 513   // width 512 + 1 metadata column
#define RESIZE_TO 256.0f

__global__ __launch_bounds__(OUT_W) void center_crop_kernel(
    const float* __restrict__ x, float* __restrict__ out)
{
    const int y = blockIdx.x;   // output row 0..223
    const int b = blockIdx.y;   // batch 0..63
    const int tx = threadIdx.x; // output col 0..223

    const size_t img_base = (size_t)b * 3 * IN_H * IN_W_STRIDE;
    const float* img = x + img_base;

    // per-image params (scalar, redundant per block — cheap)
    const float h = img[IN_W_STRIDE - 1];                      // x[b,0,0,-1]
    const float w = img[(size_t)IN_H * IN_W_STRIDE + IN_W_STRIDE - 1]; // x[b,1,0,-1]
    const float min_dim = fminf(h, w);
    const float scale = RESIZE_TO / min_dim;
    const float h_res = rintf(h * scale);
    const float w_res = rintf(w * scale);
    const float top  = rintf((h_res - (float)OUT_H) / 2.0f);
    const float left = rintf((w_res - (float)OUT_W) / 2.0f);

    const int hi = (int)h - 1;
    const int wi = (int)w - 1;

    // row (y) coordinates — same for whole block
    float src_y = (((float)y + top) + 0.5f) * h / h_res - 0.5f;
    src_y = fminf(fmaxf(src_y, 0.0f), h - 1.0f);
    const float y0f = floorf(src_y);
    const float wy = src_y - y0f;
    int y0 = (int)y0f;
    y0 = max(0, min(y0, hi));
    const int y1 = min(y0 + 1, hi);

    // column (x) coordinate — per thread
    float src_x = (((float)tx + left) + 0.5f) * w / w_res - 0.5f;
    src_x = fminf(fmaxf(src_x, 0.0f), w - 1.0f);
    const float x0f = floorf(src_x);
    const float wx = src_x - x0f;
    int x0 = (int)x0f;
    x0 = max(0, min(x0, wi));
    const int x1 = min(x0 + 1, wi);

    const size_t row0 = (size_t)y0 * IN_W_STRIDE;
    const size_t row1 = (size_t)y1 * IN_W_STRIDE;
    const size_t out_base = (size_t)b * 3 * OUT_H * OUT_W + (size_t)y * OUT_W + tx;

    #pragma unroll
    for (int c = 0; c < 3; c++) {
        const float* plane = img + (size_t)c * IN_H * IN_W_STRIDE;
        const float v00 = __ldg(plane + row0 + x0);
        const float v01 = __ldg(plane + row0 + x1);
        const float v10 = __ldg(plane + row1 + x0);
        const float v11 = __ldg(plane + row1 + x1);
        const float t0 = v00 + wx * (v01 - v00);
        const float t1 = v10 + wx * (v11 - v10);
        const float r  = t0 + wy * (t1 - t0);
        out[out_base + (size_t)c * OUT_H * OUT_W] = r;
    }
}

extern "C" void kernel_launch(void* const* d_in, const int* in_sizes, int n_in,
                              void* d_out, int out_size)
{
    const float* x = (const float*)d_in[0];
    float* out = (float*)d_out;
    dim3 grid(OUT_H, 64);
    dim3 block(OUT_W);
    center_crop_kernel<<<grid, block>>>(x, out);
}

// round 3
// speedup vs baseline: 1.0720x; 1.0720x over previous
#include <cuda_runtime.h>

// Input:  x  (B=64, C=3, H=512, W+1=513) fp32; h_orig = x[b,0,0,512], w_orig = x[b,1,0,512]
// Output: (64, 3, 224, 224) fp32
// Resize shorter side to 256 (bilinear, half-pixel centers, rint), center-crop 224x224.
// R2: 2 output rows per thread -> 24 LDGs of MLP batched before compute,
// column math computed once for both rows.

#define OUT_H 224
#define OUT_W 224
#define IN_H 512
#define IN_W_STRIDE 513
#define RESIZE_TO 256.0f
#define ROWS_PER_BLK 2

__global__ __launch_bounds__(OUT_W) void center_crop_kernel(
    const float* __restrict__ x, float* __restrict__ out)
{
    const int ypair = blockIdx.x;   // 0..111
    const int b = blockIdx.y;       // 0..63
    const int tx = threadIdx.x;     // 0..223

    const float* img = x + (size_t)b * 3 * IN_H * IN_W_STRIDE;

    // per-image params
    const float h = img[IN_W_STRIDE - 1];
    const float w = img[(size_t)IN_H * IN_W_STRIDE + IN_W_STRIDE - 1];
    const float min_dim = fminf(h, w);
    const float scale = RESIZE_TO / min_dim;
    const float h_res = rintf(h * scale);
    const float w_res = rintf(w * scale);
    const float top  = rintf((h_res - (float)OUT_H) * 0.5f);
    const float left = rintf((w_res - (float)OUT_W) * 0.5f);

    const int hi = (int)h - 1;
    const int wi = (int)w - 1;

    // column coordinate — per thread, shared by both rows
    float src_x = (((float)tx + left) + 0.5f) * w / w_res - 0.5f;
    src_x = fminf(fmaxf(src_x, 0.0f), w - 1.0f);
    const float x0f = floorf(src_x);
    const float wx = src_x - x0f;
    int x0 = (int)x0f;
    x0 = max(0, min(x0, wi));
    const int x1 = min(x0 + 1, wi);

    // row coordinates for the 2 rows this thread handles
    size_t row0[ROWS_PER_BLK], row1[ROWS_PER_BLK];
    float wy[ROWS_PER_BLK];
    #pragma unroll
    for (int r = 0; r < ROWS_PER_BLK; r++) {
        const int y = ypair * ROWS_PER_BLK + r;
        float src_y = (((float)y + top) + 0.5f) * h / h_res - 0.5f;
        src_y = fminf(fmaxf(src_y, 0.0f), h - 1.0f);
        const float y0f = floorf(src_y);
        wy[r] = src_y - y0f;
        int y0 = (int)y0f;
        y0 = max(0, min(y0, hi));
        const int y1 = min(y0 + 1, hi);
        row0[r] = (size_t)y0 * IN_W_STRIDE;
        row1[r] = (size_t)y1 * IN_W_STRIDE;
    }

    // batch ALL loads first (24 LDGs in flight), then compute
    float v00[ROWS_PER_BLK][3], v01[ROWS_PER_BLK][3];
    float v10[ROWS_PER_BLK][3], v11[ROWS_PER_BLK][3];
    #pragma unroll
    for (int c = 0; c < 3; c++) {
        const float* plane = img + (size_t)c * IN_H * IN_W_STRIDE;
        #pragma unroll
        for (int r = 0; r < ROWS_PER_BLK; r++) {
            v00[r][c] = __ldg(plane + row0[r] + x0);
            v01[r][c] = __ldg(plane + row0[r] + x1);
            v10[r][c] = __ldg(plane + row1[r] + x0);
            v11[r][c] = __ldg(plane + row1[r] + x1);
        }
    }

    const size_t out_img = (size_t)b * 3 * OUT_H * OUT_W;
    #pragma unroll
    for (int c = 0; c < 3; c++) {
        #pragma unroll
        for (int r = 0; r < ROWS_PER_BLK; r++) {
            const int y = ypair * ROWS_PER_BLK + r;
            const float t0 = v00[r][c] + wx * (v01[r][c] - v00[r][c]);
            const float t1 = v10[r][c] + wx * (v11[r][c] - v10[r][c]);
            const float res = t0 + wy[r] * (t1 - t0);
            out[out_img + (size_t)c * OUT_H * OUT_W + (size_t)y * OUT_W + tx] = res;
        }
    }
}

extern "C" void kernel_launch(void* const* d_in, const int* in_sizes, int n_in,
                              void* d_out, int out_size)
{
    const float* x = (const float*)d_in[0];
    float* out = (float*)d_out;
    dim3 grid(OUT_H / ROWS_PER_BLK, 64);
    dim3 block(OUT_W);
    center_crop_kernel<<<grid, block>>>(x, out);
}

// round 7
// speedup vs baseline: 1.1596x; 1.0817x over previous
#include <cuda_runtime.h>

// Input:  x  (B=64, C=3, H=512, W+1=513) fp32; h_orig = x[b,0,0,512], w_orig = x[b,1,0,512]
// Output: (64, 3, 224, 224) fp32
// Resize shorter side to 256 (bilinear, half-pixel centers, rint), center-crop 224x224.
// R6 = R3 resubmit (infra flake): 2 rows/thread (24-LDG MLP) + all-int32 indexing
// + forced 8 blocks/SM.

#define OUT_H 224
#define OUT_W 224
#define IN_H 512
#define IN_W_STRIDE 513
#define PLANE (IN_H * IN_W_STRIDE)      // 262656 elements, fits LDG imm offset
#define RESIZE_TO 256.0f
#define ROWS_PER_BLK 2

__global__ __launch_bounds__(OUT_W, 8) void center_crop_kernel(
    const float* __restrict__ x, float* __restrict__ out)
{
    const int ypair = blockIdx.x;   // 0..111
    const int b = blockIdx.y;       // 0..63
    const int tx = threadIdx.x;     // 0..223

    const float* img = x + b * (3 * PLANE);

    // per-image params
    const float h = img[IN_W_STRIDE - 1];
    const float w = img[PLANE + IN_W_STRIDE - 1];
    const float min_dim = fminf(h, w);
    const float scale = RESIZE_TO / min_dim;
    const float h_res = rintf(h * scale);
    const float w_res = rintf(w * scale);
    const float top  = rintf((h_res - (float)OUT_H) * 0.5f);
    const float left = rintf((w_res - (float)OUT_W) * 0.5f);

    const int hi = (int)h - 1;
    const int wi = (int)w - 1;

    // column coordinate — per thread, shared by both rows
    float src_x = (((float)tx + left) + 0.5f) * w / w_res - 0.5f;
    src_x = fminf(fmaxf(src_x, 0.0f), w - 1.0f);
    const float x0f = floorf(src_x);
    const float wx = src_x - x0f;
    int x0 = (int)x0f;
    x0 = max(0, min(x0, wi));
    const int x1 = min(x0 + 1, wi);

    // row coordinates for the 2 rows (int32 offsets)
    int off00[ROWS_PER_BLK], off01[ROWS_PER_BLK];
    int off10[ROWS_PER_BLK], off11[ROWS_PER_BLK];
    float wy[ROWS_PER_BLK];
    #pragma unroll
    for (int r = 0; r < ROWS_PER_BLK; r++) {
        const int y = ypair * ROWS_PER_BLK + r;
        float src_y = (((float)y + top) + 0.5f) * h / h_res - 0.5f;
        src_y = fminf(fmaxf(src_y, 0.0f), h - 1.0f);
        const float y0f = floorf(src_y);
        wy[r] = src_y - y0f;
        int y0 = (int)y0f;
        y0 = max(0, min(y0, hi));
        const int y1 = min(y0 + 1, hi);
        off00[r] = y0 * IN_W_STRIDE + x0;
        off01[r] = y0 * IN_W_STRIDE + x1;
        off10[r] = y1 * IN_W_STRIDE + x0;
        off11[r] = y1 * IN_W_STRIDE + x1;
    }

    // batch ALL 24 loads first, then compute (channel stride = LDG immediate)
    float v00[ROWS_PER_BLK][3], v01[ROWS_PER_BLK][3];
    float v10[ROWS_PER_BLK][3], v11[ROWS_PER_BLK][3];
    #pragma unroll
    for (int r = 0; r < ROWS_PER_BLK; r++) {
        #pragma unroll
        for (int c = 0; c < 3; c++) {
            v00[r][c] = __ldg(img + off00[r] + c * PLANE);
            v01[r][c] = __ldg(img + off01[r] + c * PLANE);
            v10[r][c] = __ldg(img + off10[r] + c * PLANE);
            v11[r][c] = __ldg(img + off11[r] + c * PLANE);
        }
    }

    const int out_base = b * (3 * OUT_H * OUT_W)
                       + (ypair * ROWS_PER_BLK) * OUT_W + tx;
    #pragma unroll
    for (int c = 0; c < 3; c++) {
        #pragma unroll
        for (int r = 0; r < ROWS_PER_BLK; r++) {
            const float t0 = v00[r][c] + wx * (v01[r][c] - v00[r][c]);
            const float t1 = v10[r][c] + wx * (v11[r][c] - v10[r][c]);
            const float res = t0 + wy[r] * (t1 - t0);
            out[out_base + c * (OUT_H * OUT_W) + r * OUT_W] = res;
        }
    }
}

extern "C" void kernel_launch(void* const* d_in, const int* in_sizes, int n_in,
                              void* d_out, int out_size)
{
    const float* x = (const float*)d_in[0];
    float* out = (float*)d_out;
    dim3 grid(OUT_H / ROWS_PER_BLK, 64);
    dim3 block(OUT_W);
    center_crop_kernel<<<grid, block>>>(x, out);
}